// round 1
// baseline (speedup 1.0000x reference)
#include <cuda_runtime.h>
#include <math.h>

#define B_ 16
#define T_ 2048
#define C_ 512
#define H_ 64

// Scratch for projected q,k,v  (8 MB each — __device__ globals are the allowed scratch path)
__device__ float g_q[B_*T_*H_];
__device__ float g_k[B_*T_*H_];
__device__ float g_v[B_*T_*H_];

// ---------------------------------------------------------------------------
// Kernel 1: fused QKV projection.  out[row][h] = sum_c x[row][c] * W[c][h]
// grid = (512 row-tiles, 3 matrices), block = 256
// ---------------------------------------------------------------------------
__global__ __launch_bounds__(256) void proj_kernel(
    const float* __restrict__ x,
    const float* __restrict__ Wq,
    const float* __restrict__ Wk,
    const float* __restrict__ Wv)
{
    __shared__ float sXt[64*68];   // [kk][r]  (transposed chunk of x)
    __shared__ float sW [64*68];   // [kk][h]
    const int tid  = threadIdx.x;
    const int tx   = tid & 15;
    const int ty   = tid >> 4;
    const int lane = tid & 63;
    const int grp  = tid >> 6;
    const int row0 = blockIdx.x * 64;

    const float* __restrict__ W;
    float* __restrict__ outp;
    if (blockIdx.y == 0)      { W = Wq; outp = g_q; }
    else if (blockIdx.y == 1) { W = Wk; outp = g_k; }
    else                      { W = Wv; outp = g_v; }

    float acc[4][4];
    #pragma unroll
    for (int i = 0; i < 4; ++i)
        #pragma unroll
        for (int j = 0; j < 4; ++j) acc[i][j] = 0.f;

    for (int kc = 0; kc < C_; kc += 64) {
        __syncthreads();
        #pragma unroll
        for (int it = 0; it < 16; ++it) {
            int r = grp + it * 4;
            sXt[lane*68 + r] = x[(size_t)(row0 + r) * C_ + kc + lane];
        }
        #pragma unroll
        for (int it = 0; it < 16; ++it) {
            int kk = grp + it * 4;
            sW[kk*68 + lane] = W[(size_t)(kc + kk) * H_ + lane];
        }
        __syncthreads();
        #pragma unroll 8
        for (int kk = 0; kk < 64; ++kk) {
            float4 xv = *(const float4*)&sXt[kk*68 + ty*4];
            float4 wv = *(const float4*)&sW [kk*68 + tx*4];
            float xa[4] = {xv.x, xv.y, xv.z, xv.w};
            float wb[4] = {wv.x, wv.y, wv.z, wv.w};
            #pragma unroll
            for (int i = 0; i < 4; ++i)
                #pragma unroll
                for (int j = 0; j < 4; ++j)
                    acc[i][j] += xa[i] * wb[j];
        }
    }
    #pragma unroll
    for (int i = 0; i < 4; ++i) {
        float4 res = make_float4(acc[i][0], acc[i][1], acc[i][2], acc[i][3]);
        *(float4*)&outp[(size_t)(row0 + ty*4 + i) * H_ + tx*4] = res;
    }
}

// ---------------------------------------------------------------------------
// Kernel 2: causal flash attention with skewed relative bias.
//   att[t,s] = 0.125*q[t].k[s] + rel,   rel: s==t -> q[t].Er[T-1];
//   s==t-1 -> 0;  s<=t-2 -> q[s+1].Er[t-s-2]
// Rel handled per tile via banded GEMM  G[a][c] = ErBand[a].qcol[c],
// gathered as S[r][c] += G[r-c+63][c]  (OOB Er rows zero-filled).
// grid = (32 row-tiles, 16 batches), block = 256, ~152 KB dyn smem.
// ---------------------------------------------------------------------------

// float offsets into dynamic shared memory
#define OFF_QT    0        // [h][r]  64x68
#define OFF_KT    4352     // [h][c]  64x68
#define OFF_QCT   8704     // [h][c]  64x68  (q rows s0+1..s0+64, transposed)
#define OFF_V     13056    // [c][h]  64x68
#define OFF_PT    17408    // [c][r]  64x68
#define OFF_ET    21760    // [h][a]  64x132 (Er band, transposed)
#define OFF_G     30208    // [a][c]  128x68
#define OFF_DIAG  38912    // [r]     64
#define SMEM_FLOATS 38976
#define SMEM_BYTES  (SMEM_FLOATS*4)

__global__ __launch_bounds__(256) void attn_kernel(
    const float* __restrict__ Er,
    float* __restrict__ out)
{
    extern __shared__ float sm[];
    float* sQt   = sm + OFF_QT;
    float* sKt   = sm + OFF_KT;
    float* sQct  = sm + OFF_QCT;
    float* sV    = sm + OFF_V;
    float* sPt   = sm + OFF_PT;
    float* sEt   = sm + OFF_ET;
    float* sG    = sm + OFF_G;
    float* sDiag = sm + OFF_DIAG;

    const int tid  = threadIdx.x;
    const int tx   = tid & 15;
    const int ty   = tid >> 4;
    const int lane = tid & 63;
    const int grp  = tid >> 6;
    const int m    = 31 - (int)blockIdx.x;   // big tiles scheduled first
    const int b    = blockIdx.y;
    const int t0   = m * 64;
    const size_t bT = (size_t)b * T_;

    // ---- prologue: Q row tile (transposed) ----
    #pragma unroll
    for (int it = 0; it < 16; ++it) {
        int r = grp + it * 4;
        sQt[lane*68 + r] = g_q[(bT + t0 + r) * H_ + lane];
    }
    __syncthreads();

    // diag[r] = q[t0+r] . Er[T-1]
    {
        int r = tid >> 2, part = tid & 3;
        float p = 0.f;
        const float* er = Er + (size_t)(T_-1) * H_;
        #pragma unroll
        for (int hh = 0; hh < 16; ++hh) {
            int h = part*16 + hh;
            p += sQt[h*68 + r] * er[h];
        }
        p += __shfl_xor_sync(0xffffffffu, p, 1);
        p += __shfl_xor_sync(0xffffffffu, p, 2);
        if (part == 0) sDiag[r] = p;
    }

    float o[4][4];
    float mrow[4], lrow[4];
    #pragma unroll
    for (int i = 0; i < 4; ++i) {
        mrow[i] = -3.0e38f;
        lrow[i] = 0.f;
        #pragma unroll
        for (int jj = 0; jj < 4; ++jj) o[i][jj] = 0.f;
    }

    for (int jt = 0; jt <= m; ++jt) {
        const int s0 = jt * 64;
        const int d  = t0 - s0;
        __syncthreads();

        // ---- loads ----
        #pragma unroll
        for (int it = 0; it < 16; ++it) {
            int c = grp + it * 4;
            sKt[lane*68 + c] = g_k[(bT + s0 + c) * H_ + lane];
            sV [c*68 + lane] = g_v[(bT + s0 + c) * H_ + lane];
            int qr = s0 + 1 + c;
            sQct[lane*68 + c] = (qr < T_) ? g_q[(bT + qr) * H_ + lane] : 0.f;
        }
        #pragma unroll
        for (int it = 0; it < 32; ++it) {
            int a = grp + it * 4;
            int e = d - 65 + a;                 // Er row; e<0 => contributes 0
            sEt[lane*132 + a] = (e >= 0) ? Er[(size_t)e * H_ + lane] : 0.f;
        }
        __syncthreads();

        // ---- G = ErBand (128) x Qcol^T (64), inner dim h ----
        #pragma unroll
        for (int p = 0; p < 2; ++p) {
            float g0[4][4];
            #pragma unroll
            for (int i = 0; i < 4; ++i)
                #pragma unroll
                for (int jj = 0; jj < 4; ++jj) g0[i][jj] = 0.f;
            #pragma unroll 8
            for (int h = 0; h < 64; ++h) {
                float4 ev = *(const float4*)&sEt[h*132 + p*64 + ty*4];
                float4 qv = *(const float4*)&sQct[h*68 + tx*4];
                float ea[4] = {ev.x, ev.y, ev.z, ev.w};
                float qb[4] = {qv.x, qv.y, qv.z, qv.w};
                #pragma unroll
                for (int i = 0; i < 4; ++i)
                    #pragma unroll
                    for (int jj = 0; jj < 4; ++jj)
                        g0[i][jj] += ea[i] * qb[jj];
            }
            #pragma unroll
            for (int i = 0; i < 4; ++i) {
                float4 res = make_float4(g0[i][0], g0[i][1], g0[i][2], g0[i][3]);
                *(float4*)&sG[(p*64 + ty*4 + i)*68 + tx*4] = res;
            }
        }
        __syncthreads();

        // ---- S = Qrow x K^T ----
        float s_[4][4];
        #pragma unroll
        for (int i = 0; i < 4; ++i)
            #pragma unroll
            for (int jj = 0; jj < 4; ++jj) s_[i][jj] = 0.f;
        #pragma unroll 8
        for (int h = 0; h < 64; ++h) {
            float4 qv = *(const float4*)&sQt[h*68 + ty*4];
            float4 kv = *(const float4*)&sKt[h*68 + tx*4];
            float qa[4] = {qv.x, qv.y, qv.z, qv.w};
            float kb[4] = {kv.x, kv.y, kv.z, kv.w};
            #pragma unroll
            for (int i = 0; i < 4; ++i)
                #pragma unroll
                for (int jj = 0; jj < 4; ++jj)
                    s_[i][jj] += qa[i] * kb[jj];
        }

        // ---- assemble scores ----
        const bool diagTile = (jt == m);
        float val[4][4];
        #pragma unroll
        for (int i = 0; i < 4; ++i) {
            int r = ty*4 + i;
            #pragma unroll
            for (int jj = 0; jj < 4; ++jj) {
                int c = tx*4 + jj;
                float v = s_[i][jj] * 0.125f + sG[(r - c + 63)*68 + c];
                if (diagTile) {
                    if (c == r)      v += sDiag[r];
                    else if (c > r)  v = -3.0e38f;
                }
                val[i][jj] = v;
            }
        }

        // ---- online softmax (rows spread over 16 lanes of a half-warp) ----
        #pragma unroll
        for (int i = 0; i < 4; ++i) {
            float mt = fmaxf(fmaxf(val[i][0], val[i][1]), fmaxf(val[i][2], val[i][3]));
            #pragma unroll
            for (int off = 1; off < 16; off <<= 1)
                mt = fmaxf(mt, __shfl_xor_sync(0xffffffffu, mt, off));
            float mnew = fmaxf(mrow[i], mt);
            float corr = expf(mrow[i] - mnew);
            mrow[i] = mnew;
            float sum = 0.f;
            #pragma unroll
            for (int jj = 0; jj < 4; ++jj) {
                float p = expf(val[i][jj] - mnew);
                val[i][jj] = p;
                sum += p;
            }
            #pragma unroll
            for (int off = 1; off < 16; off <<= 1)
                sum += __shfl_xor_sync(0xffffffffu, sum, off);
            lrow[i] = lrow[i] * corr + sum;
            #pragma unroll
            for (int jj = 0; jj < 4; ++jj) {
                o[i][jj] *= corr;
                sPt[(tx*4 + jj)*68 + ty*4 + i] = val[i][jj];
            }
        }
        __syncthreads();

        // ---- O += P x V ----
        #pragma unroll 8
        for (int c = 0; c < 64; ++c) {
            float4 pv = *(const float4*)&sPt[c*68 + ty*4];
            float4 vv = *(const float4*)&sV [c*68 + tx*4];
            float pa[4] = {pv.x, pv.y, pv.z, pv.w};
            float vb[4] = {vv.x, vv.y, vv.z, vv.w};
            #pragma unroll
            for (int i = 0; i < 4; ++i)
                #pragma unroll
                for (int jj = 0; jj < 4; ++jj)
                    o[i][jj] += pa[i] * vb[jj];
        }
    }

    // ---- epilogue ----
    #pragma unroll
    for (int i = 0; i < 4; ++i) {
        float inv = 1.f / lrow[i];
        float4 res = make_float4(o[i][0]*inv, o[i][1]*inv, o[i][2]*inv, o[i][3]*inv);
        *(float4*)&out[(bT + t0 + ty*4 + i) * H_ + tx*4] = res;
    }
}

// ---------------------------------------------------------------------------
extern "C" void kernel_launch(void* const* d_in, const int* in_sizes, int n_in,
                              void* d_out, int out_size)
{
    const float* x  = (const float*)d_in[0];
    const float* Wq = (const float*)d_in[1];
    const float* Wk = (const float*)d_in[2];
    const float* Wv = (const float*)d_in[3];
    const float* Er = (const float*)d_in[4];
    float* out = (float*)d_out;

    cudaFuncSetAttribute(attn_kernel,
                         cudaFuncAttributeMaxDynamicSharedMemorySize, SMEM_BYTES);

    proj_kernel<<<dim3(512, 3), 256>>>(x, Wq, Wk, Wv);
    attn_kernel<<<dim3(32, 16), 256, SMEM_BYTES>>>(Er, out);
}

// round 2
// speedup vs baseline: 1.1525x; 1.1525x over previous
#include <cuda_runtime.h>
#include <math.h>
#include <stdint.h>

#define B_ 16
#define T_ 2048
#define C_ 512
#define H_ 64

// Scratch for projected q,k,v (__device__ globals = allowed scratch path)
__device__ float g_q[B_*T_*H_];
__device__ float g_k[B_*T_*H_];
__device__ float g_v[B_*T_*H_];

// ---------------------------------------------------------------------------
// tf32 helpers: 3xTF32 split precision. smem stays fp32; hi/lo derived in regs.
// ---------------------------------------------------------------------------
__device__ __forceinline__ uint32_t tf32_of(float x) {
    uint32_t u;
    asm("cvt.rna.tf32.f32 %0, %1;" : "=r"(u) : "f"(x));
    return u;
}
struct TF2 { uint32_t hi, lo; };
__device__ __forceinline__ TF2 tf32_split(float x) {
    TF2 r;
    r.hi = tf32_of(x);
    r.lo = tf32_of(x - __uint_as_float(r.hi));
    return r;
}
__device__ __forceinline__ void mma8(float* c,
    uint32_t a0, uint32_t a1, uint32_t a2, uint32_t a3,
    uint32_t b0, uint32_t b1)
{
    asm volatile(
        "mma.sync.aligned.m16n8k8.row.col.f32.tf32.tf32.f32 "
        "{%0,%1,%2,%3}, {%4,%5,%6,%7}, {%8,%9}, {%0,%1,%2,%3};"
        : "+f"(c[0]), "+f"(c[1]), "+f"(c[2]), "+f"(c[3])
        : "r"(a0), "r"(a1), "r"(a2), "r"(a3), "r"(b0), "r"(b1));
}

// acc[8][4] += A(16 rows of sA starting arow0, k=64) x B^T
// B stored row-major [n][k] ("Bt"): sB[n*68 + k]
__device__ __forceinline__ void gemm_split_Bt(
    const float* __restrict__ sA, int arow0,
    const float* __restrict__ sB, int lane, float (*acc)[4])
{
    const int gid = lane >> 2, tig = lane & 3;
    #pragma unroll
    for (int kk = 0; kk < 8; ++kk) {
        const int kb = kk * 8;
        TF2 a0 = tf32_split(sA[(arow0+gid  )*68 + kb + tig    ]);
        TF2 a1 = tf32_split(sA[(arow0+gid+8)*68 + kb + tig    ]);
        TF2 a2 = tf32_split(sA[(arow0+gid  )*68 + kb + tig + 4]);
        TF2 a3 = tf32_split(sA[(arow0+gid+8)*68 + kb + tig + 4]);
        #pragma unroll
        for (int n = 0; n < 8; ++n) {
            TF2 b0 = tf32_split(sB[(n*8+gid)*68 + kb + tig    ]);
            TF2 b1 = tf32_split(sB[(n*8+gid)*68 + kb + tig + 4]);
            mma8(acc[n], a0.hi, a1.hi, a2.hi, a3.hi, b0.hi, b1.hi);
            mma8(acc[n], a0.lo, a1.lo, a2.lo, a3.lo, b0.hi, b1.hi);
            mma8(acc[n], a0.hi, a1.hi, a2.hi, a3.hi, b0.lo, b1.lo);
        }
    }
}

// Same, but B stored row-major [k][n] ("Bn"): sB[k*68 + n]   (used for PV)
__device__ __forceinline__ void gemm_split_Bn(
    const float* __restrict__ sA, int arow0,
    const float* __restrict__ sB, int lane, float (*acc)[4])
{
    const int gid = lane >> 2, tig = lane & 3;
    #pragma unroll
    for (int kk = 0; kk < 8; ++kk) {
        const int kb = kk * 8;
        TF2 a0 = tf32_split(sA[(arow0+gid  )*68 + kb + tig    ]);
        TF2 a1 = tf32_split(sA[(arow0+gid+8)*68 + kb + tig    ]);
        TF2 a2 = tf32_split(sA[(arow0+gid  )*68 + kb + tig + 4]);
        TF2 a3 = tf32_split(sA[(arow0+gid+8)*68 + kb + tig + 4]);
        #pragma unroll
        for (int n = 0; n < 8; ++n) {
            TF2 b0 = tf32_split(sB[(kb + tig    )*68 + n*8 + gid]);
            TF2 b1 = tf32_split(sB[(kb + tig + 4)*68 + n*8 + gid]);
            mma8(acc[n], a0.hi, a1.hi, a2.hi, a3.hi, b0.hi, b1.hi);
            mma8(acc[n], a0.lo, a1.lo, a2.lo, a3.lo, b0.hi, b1.hi);
            mma8(acc[n], a0.hi, a1.hi, a2.hi, a3.hi, b0.lo, b1.lo);
        }
    }
}

// ---------------------------------------------------------------------------
// Kernel 1: fused QKV projection (unchanged SIMT from R1)
// ---------------------------------------------------------------------------
__global__ __launch_bounds__(256) void proj_kernel(
    const float* __restrict__ x,
    const float* __restrict__ Wq,
    const float* __restrict__ Wk,
    const float* __restrict__ Wv)
{
    __shared__ float sXt[64*68];
    __shared__ float sW [64*68];
    const int tid  = threadIdx.x;
    const int tx   = tid & 15;
    const int ty   = tid >> 4;
    const int lane = tid & 63;
    const int grp  = tid >> 6;
    const int row0 = blockIdx.x * 64;

    const float* __restrict__ W;
    float* __restrict__ outp;
    if (blockIdx.y == 0)      { W = Wq; outp = g_q; }
    else if (blockIdx.y == 1) { W = Wk; outp = g_k; }
    else                      { W = Wv; outp = g_v; }

    float acc[4][4];
    #pragma unroll
    for (int i = 0; i < 4; ++i)
        #pragma unroll
        for (int j = 0; j < 4; ++j) acc[i][j] = 0.f;

    for (int kc = 0; kc < C_; kc += 64) {
        __syncthreads();
        #pragma unroll
        for (int it = 0; it < 16; ++it) {
            int r = grp + it * 4;
            sXt[lane*68 + r] = x[(size_t)(row0 + r) * C_ + kc + lane];
        }
        #pragma unroll
        for (int it = 0; it < 16; ++it) {
            int kk = grp + it * 4;
            sW[kk*68 + lane] = W[(size_t)(kc + kk) * H_ + lane];
        }
        __syncthreads();
        #pragma unroll 8
        for (int kk = 0; kk < 64; ++kk) {
            float4 xv = *(const float4*)&sXt[kk*68 + ty*4];
            float4 wv = *(const float4*)&sW [kk*68 + tx*4];
            float xa[4] = {xv.x, xv.y, xv.z, xv.w};
            float wb[4] = {wv.x, wv.y, wv.z, wv.w};
            #pragma unroll
            for (int i = 0; i < 4; ++i)
                #pragma unroll
                for (int j = 0; j < 4; ++j)
                    acc[i][j] += xa[i] * wb[j];
        }
    }
    #pragma unroll
    for (int i = 0; i < 4; ++i) {
        float4 res = make_float4(acc[i][0], acc[i][1], acc[i][2], acc[i][3]);
        *(float4*)&outp[(size_t)(row0 + ty*4 + i) * H_ + tx*4] = res;
    }
}

// ---------------------------------------------------------------------------
// Kernel 2: tensor-core (3xtf32 mma.sync) causal flash attention with skewed
// relative bias. block = 128 (4 warps); warp w owns tile rows [w*16, w*16+16).
//   att[t,s] = 0.125*q[t].k[s] + rel; rel(t,t)=q[t].Er[T-1]; rel(t,t-1)=0;
//   rel(t,s)=q[s+1].Er[t-s-2] (s<=t-2), via banded GEMM G + diagonal gather:
//   S[r][c] += G[r-c+63][c],  G[a][c] = Er[d-65+a].q[s0+1+c]  (OOB -> 0).
// ---------------------------------------------------------------------------
#define SQ_OFF    0
#define SK_OFF    4352
#define SQC_OFF   8704
#define SV_OFF    13056
#define SP_OFF    17408
#define SE_OFF    21760      /* 128x68 */
#define SG_OFF    30464      /* 128x68 */
#define SDIAG_OFF 39168
#define SMEM_FLOATS 39232
#define SMEM_BYTES (SMEM_FLOATS*4)

__global__ __launch_bounds__(128) void attn_kernel(
    const float* __restrict__ Er,
    float* __restrict__ out)
{
    extern __shared__ float sm[];
    float* sQ    = sm + SQ_OFF;
    float* sK    = sm + SK_OFF;
    float* sQc   = sm + SQC_OFF;
    float* sV    = sm + SV_OFF;
    float* sP    = sm + SP_OFF;
    float* sE    = sm + SE_OFF;
    float* sG    = sm + SG_OFF;
    float* sDiag = sm + SDIAG_OFF;

    const int tid  = threadIdx.x;
    const int w    = tid >> 5;
    const int lane = tid & 31;
    const int gid  = lane >> 2;
    const int tig  = lane & 3;
    const int m    = 31 - (int)blockIdx.x;    // big tiles first
    const int b    = blockIdx.y;
    const int t0   = m * 64;
    const size_t bT = (size_t)b * T_;

    #pragma unroll
    for (int i = 0; i < 8; ++i) {
        int lin = tid + i * 128;
        int r = lin >> 4, h4 = (lin & 15) * 4;
        *(float4*)&sQ[r*68 + h4] = *(const float4*)&g_q[(bT + t0 + r)*H_ + h4];
    }
    __syncthreads();

    {   // diag[r] = q[t0+r] . Er[T-1]
        int r = tid >> 1, half = tid & 1;
        const float* er = Er + (size_t)(T_-1) * H_;
        float p = 0.f;
        #pragma unroll
        for (int hh = 0; hh < 32; ++hh) {
            int h = half*32 + hh;
            p += sQ[r*68 + h] * er[h];
        }
        p += __shfl_xor_sync(0xffffffffu, p, 1);
        if (half == 0) sDiag[r] = p;
    }

    float o[8][4];
    float mrow[2], lrow[2];
    #pragma unroll
    for (int n = 0; n < 8; ++n)
        #pragma unroll
        for (int j = 0; j < 4; ++j) o[n][j] = 0.f;
    mrow[0] = mrow[1] = -3.0e38f;
    lrow[0] = lrow[1] = 0.f;

    const int r0 = w*16 + gid;

    for (int jt = 0; jt <= m; ++jt) {
        const int s0 = jt * 64;
        const int d  = t0 - s0;
        __syncthreads();

        #pragma unroll
        for (int i = 0; i < 8; ++i) {
            int lin = tid + i * 128;
            int rr = lin >> 4, h4 = (lin & 15) * 4;
            *(float4*)&sK[rr*68 + h4] = *(const float4*)&g_k[(bT + s0 + rr)*H_ + h4];
            *(float4*)&sV[rr*68 + h4] = *(const float4*)&g_v[(bT + s0 + rr)*H_ + h4];
            int qr = s0 + 1 + rr;
            float4 qv = make_float4(0.f,0.f,0.f,0.f);
            if (qr < T_) qv = *(const float4*)&g_q[(bT + qr)*H_ + h4];
            *(float4*)&sQc[rr*68 + h4] = qv;
        }
        #pragma unroll
        for (int i = 0; i < 16; ++i) {
            int lin = tid + i * 128;
            int a = lin >> 4, h4 = (lin & 15) * 4;
            int e = d - 65 + a;
            float4 ev = make_float4(0.f,0.f,0.f,0.f);
            if (e >= 0) ev = *(const float4*)&Er[(size_t)e*H_ + h4];
            *(float4*)&sE[a*68 + h4] = ev;
        }
        __syncthreads();

        // G = ErBand(128) x Qc^T
        #pragma unroll
        for (int mt = 0; mt < 2; ++mt) {
            float g[8][4];
            #pragma unroll
            for (int n = 0; n < 8; ++n)
                #pragma unroll
                for (int j = 0; j < 4; ++j) g[n][j] = 0.f;
            const int ar0 = w*32 + mt*16;
            gemm_split_Bt(sE, ar0, sQc, lane, g);
            const int ar = ar0 + gid;
            #pragma unroll
            for (int n = 0; n < 8; ++n) {
                *(float2*)&sG[ ar   *68 + n*8 + 2*tig] = make_float2(g[n][0], g[n][1]);
                *(float2*)&sG[(ar+8)*68 + n*8 + 2*tig] = make_float2(g[n][2], g[n][3]);
            }
        }

        // S = Q x K^T
        float s[8][4];
        #pragma unroll
        for (int n = 0; n < 8; ++n)
            #pragma unroll
            for (int j = 0; j < 4; ++j) s[n][j] = 0.f;
        gemm_split_Bt(sQ, w*16, sK, lane, s);
        __syncthreads();

        // assemble + online softmax
        const bool dt = (jt == m);
        float mt0 = -3.0e38f, mt1 = -3.0e38f;
        #pragma unroll
        for (int n = 0; n < 8; ++n) {
            #pragma unroll
            for (int j = 0; j < 4; ++j) {
                int r = r0 + ((j >= 2) ? 8 : 0);
                int c = n*8 + 2*tig + (j & 1);
                float v = s[n][j] * 0.125f + sG[(r - c + 63)*68 + c];
                if (dt) {
                    if (c > r)       v = -3.0e38f;
                    else if (c == r) v += sDiag[r];
                }
                s[n][j] = v;
                if (j < 2) mt0 = fmaxf(mt0, v);
                else       mt1 = fmaxf(mt1, v);
            }
        }
        mt0 = fmaxf(mt0, __shfl_xor_sync(0xffffffffu, mt0, 1));
        mt0 = fmaxf(mt0, __shfl_xor_sync(0xffffffffu, mt0, 2));
        mt1 = fmaxf(mt1, __shfl_xor_sync(0xffffffffu, mt1, 1));
        mt1 = fmaxf(mt1, __shfl_xor_sync(0xffffffffu, mt1, 2));

        float mn0 = fmaxf(mrow[0], mt0);
        float mn1 = fmaxf(mrow[1], mt1);
        float cor0 = __expf(mrow[0] - mn0);
        float cor1 = __expf(mrow[1] - mn1);
        mrow[0] = mn0; mrow[1] = mn1;

        float sum0 = 0.f, sum1 = 0.f;
        #pragma unroll
        for (int n = 0; n < 8; ++n) {
            float p0 = __expf(s[n][0] - mn0);
            float p1 = __expf(s[n][1] - mn0);
            float p2 = __expf(s[n][2] - mn1);
            float p3 = __expf(s[n][3] - mn1);
            sum0 += p0 + p1; sum1 += p2 + p3;
            *(float2*)&sP[ r0   *68 + n*8 + 2*tig] = make_float2(p0, p1);
            *(float2*)&sP[(r0+8)*68 + n*8 + 2*tig] = make_float2(p2, p3);
            o[n][0] *= cor0; o[n][1] *= cor0;
            o[n][2] *= cor1; o[n][3] *= cor1;
        }
        sum0 += __shfl_xor_sync(0xffffffffu, sum0, 1);
        sum0 += __shfl_xor_sync(0xffffffffu, sum0, 2);
        sum1 += __shfl_xor_sync(0xffffffffu, sum1, 1);
        sum1 += __shfl_xor_sync(0xffffffffu, sum1, 2);
        lrow[0] = lrow[0] * cor0 + sum0;
        lrow[1] = lrow[1] * cor1 + sum1;
        __syncthreads();

        // O += P x V
        gemm_split_Bn(sP, w*16, sV, lane, o);
    }

    float inv0 = 1.f / lrow[0];
    float inv1 = 1.f / lrow[1];
    #pragma unroll
    for (int n = 0; n < 8; ++n) {
        *(float2*)&out[(bT + t0 + r0    )*H_ + n*8 + 2*tig] =
            make_float2(o[n][0]*inv0, o[n][1]*inv0);
        *(float2*)&out[(bT + t0 + r0 + 8)*H_ + n*8 + 2*tig] =
            make_float2(o[n][2]*inv1, o[n][3]*inv1);
    }
}

// ---------------------------------------------------------------------------
extern "C" void kernel_launch(void* const* d_in, const int* in_sizes, int n_in,
                              void* d_out, int out_size)
{
    const float* x  = (const float*)d_in[0];
    const float* Wq = (const float*)d_in[1];
    const float* Wk = (const float*)d_in[2];
    const float* Wv = (const float*)d_in[3];
    const float* Er = (const float*)d_in[4];
    float* out = (float*)d_out;

    cudaFuncSetAttribute(attn_kernel,
                         cudaFuncAttributeMaxDynamicSharedMemorySize, SMEM_BYTES);

    proj_kernel<<<dim3(512, 3), 256>>>(x, Wq, Wk, Wv);
    attn_kernel<<<dim3(32, 16), 128, SMEM_BYTES>>>(Er, out);
}

// round 3
// speedup vs baseline: 1.3342x; 1.1577x over previous
#include <cuda_runtime.h>
#include <math.h>
#include <stdint.h>

#define B_ 16
#define T_ 2048
#define C_ 512
#define H_ 64

// Scratch for projected q,k,v (__device__ globals = allowed scratch path)
__device__ float g_q[B_*T_*H_];
__device__ float g_k[B_*T_*H_];
__device__ float g_v[B_*T_*H_];

// ---------------------------------------------------------------------------
// tf32 helpers
// ---------------------------------------------------------------------------
__device__ __forceinline__ uint32_t tf32_of(float x) {
    uint32_t u;
    asm("cvt.rna.tf32.f32 %0, %1;" : "=r"(u) : "f"(x));
    return u;
}
struct TF2 { uint32_t hi, lo; };
__device__ __forceinline__ TF2 tf32_split(float x) {
    TF2 r;
    r.hi = tf32_of(x);
    r.lo = tf32_of(x - __uint_as_float(r.hi));
    return r;
}
__device__ __forceinline__ float2 split_f2(float x) {
    TF2 t = tf32_split(x);
    return make_float2(__uint_as_float(t.hi), __uint_as_float(t.lo));
}
__device__ __forceinline__ void mma8(float* c,
    uint32_t a0, uint32_t a1, uint32_t a2, uint32_t a3,
    uint32_t b0, uint32_t b1)
{
    asm volatile(
        "mma.sync.aligned.m16n8k8.row.col.f32.tf32.tf32.f32 "
        "{%0,%1,%2,%3}, {%4,%5,%6,%7}, {%8,%9}, {%0,%1,%2,%3};"
        : "+f"(c[0]), "+f"(c[1]), "+f"(c[2]), "+f"(c[3])
        : "r"(a0), "r"(a1), "r"(a2), "r"(a3), "r"(b0), "r"(b1));
}

// acc[NB][4] += A(16 rows from sA @arow0, fp32, split in reg) x B^T
// B pre-split in smem as float2(hi,lo), row-major [n][k], stride 68 float2.
template<int NB>
__device__ __forceinline__ void gemm_As_B2(
    const float* __restrict__ sA, int arow0,
    const float2* __restrict__ sB2, int n0, int lane, float (*acc)[4])
{
    const int gid = lane >> 2, tig = lane & 3;
    #pragma unroll
    for (int kk = 0; kk < 8; ++kk) {
        const int kb = kk * 8;
        TF2 a0 = tf32_split(sA[(arow0+gid  )*68 + kb + tig    ]);
        TF2 a1 = tf32_split(sA[(arow0+gid+8)*68 + kb + tig    ]);
        TF2 a2 = tf32_split(sA[(arow0+gid  )*68 + kb + tig + 4]);
        TF2 a3 = tf32_split(sA[(arow0+gid+8)*68 + kb + tig + 4]);
        #pragma unroll
        for (int n = 0; n < NB; ++n) {
            float2 b0 = sB2[((n0+n)*8+gid)*68 + kb + tig    ];
            float2 b1 = sB2[((n0+n)*8+gid)*68 + kb + tig + 4];
            uint32_t b0h = __float_as_uint(b0.x), b0l = __float_as_uint(b0.y);
            uint32_t b1h = __float_as_uint(b1.x), b1l = __float_as_uint(b1.y);
            mma8(acc[n], a0.hi, a1.hi, a2.hi, a3.hi, b0h, b1h);
            mma8(acc[n], a0.lo, a1.lo, a2.lo, a3.lo, b0h, b1h);
            mma8(acc[n], a0.hi, a1.hi, a2.hi, a3.hi, b0l, b1l);
        }
    }
}

// acc[4][4] += P x V, both already tf32 bits stored as float in smem (single)
__device__ __forceinline__ void gemm_pv(
    const float* __restrict__ sPb, int arow0,
    const float* __restrict__ sVb, int n0, int lane, float (*acc)[4])
{
    const int gid = lane >> 2, tig = lane & 3;
    #pragma unroll
    for (int kk = 0; kk < 8; ++kk) {
        const int kb = kk * 8;
        uint32_t a0 = __float_as_uint(sPb[(arow0+gid  )*68 + kb + tig    ]);
        uint32_t a1 = __float_as_uint(sPb[(arow0+gid+8)*68 + kb + tig    ]);
        uint32_t a2 = __float_as_uint(sPb[(arow0+gid  )*68 + kb + tig + 4]);
        uint32_t a3 = __float_as_uint(sPb[(arow0+gid+8)*68 + kb + tig + 4]);
        #pragma unroll
        for (int n = 0; n < 4; ++n) {
            uint32_t b0 = __float_as_uint(sVb[((n0+n)*8+gid)*68 + kb + tig    ]);
            uint32_t b1 = __float_as_uint(sVb[((n0+n)*8+gid)*68 + kb + tig + 4]);
            mma8(acc[n], a0, a1, a2, a3, b0, b1);
        }
    }
}

// ---------------------------------------------------------------------------
// Kernel 1: fused QKV projection via 3xtf32 mma.
// grid = 256 CTAs (128 rows each), 256 threads (8 warps x 16 rows).
// smem: sX 128x68 plain; sW2 float2[192x68] (all three W, transposed, split).
// ---------------------------------------------------------------------------
#define PSX_OFF 0
#define PSW_OFF 8704
#define PSMEM_FLOATS (8704 + 26112)
#define PSMEM_BYTES  (PSMEM_FLOATS*4)

__global__ __launch_bounds__(256) void proj_kernel(
    const float* __restrict__ x,
    const float* __restrict__ Wq,
    const float* __restrict__ Wk,
    const float* __restrict__ Wv)
{
    extern __shared__ float sm[];
    float*  sX  = sm + PSX_OFF;
    float2* sW2 = (float2*)(sm + PSW_OFF);

    const int tid  = threadIdx.x;
    const int w    = tid >> 5;
    const int lane = tid & 31;
    const int gid  = lane >> 2;
    const int tig  = lane & 3;
    const int row0 = blockIdx.x * 128;

    float acc[24][4];
    #pragma unroll
    for (int n = 0; n < 24; ++n)
        #pragma unroll
        for (int j = 0; j < 4; ++j) acc[n][j] = 0.f;

    for (int kc = 0; kc < C_; kc += 64) {
        __syncthreads();
        {   // x chunk -> sX (plain fp32)
            int r = tid >> 1, c0 = (tid & 1) * 32;
            const float4* xp = (const float4*)&x[(size_t)(row0 + r) * C_ + kc + c0];
            #pragma unroll
            for (int u = 0; u < 8; ++u)
                *(float4*)&sX[r*68 + c0 + u*4] = xp[u];
        }
        {   // W chunks (3 matrices) -> sW2 transposed + split
            int c = tid >> 2, h0 = (tid & 3) * 16;
            const float* Ws[3] = {Wq, Wk, Wv};
            #pragma unroll
            for (int mm = 0; mm < 3; ++mm) {
                const float4* wp = (const float4*)&Ws[mm][(size_t)(kc + c) * H_ + h0];
                #pragma unroll
                for (int u = 0; u < 4; ++u) {
                    float4 wv = wp[u];
                    int hb = mm*64 + h0 + u*4;
                    sW2[(hb+0)*68 + c] = split_f2(wv.x);
                    sW2[(hb+1)*68 + c] = split_f2(wv.y);
                    sW2[(hb+2)*68 + c] = split_f2(wv.z);
                    sW2[(hb+3)*68 + c] = split_f2(wv.w);
                }
            }
        }
        __syncthreads();
        gemm_As_B2<24>(sX, w*16, sW2, 0, lane, acc);
    }

    float* outs[3] = {g_q, g_k, g_v};
    const int r = row0 + w*16 + gid;
    #pragma unroll
    for (int n = 0; n < 24; ++n) {
        int mm = n >> 3;
        int h0 = (n & 7)*8 + 2*tig;
        *(float2*)&outs[mm][(size_t)r*H_ + h0]     = make_float2(acc[n][0], acc[n][1]);
        *(float2*)&outs[mm][(size_t)(r+8)*H_ + h0] = make_float2(acc[n][2], acc[n][3]);
    }
}

// ---------------------------------------------------------------------------
// Kernel 2: 3xtf32 mma causal flash attention with skewed relative bias.
// 256 threads (8 warps). Warp w: wr=w&3 (rows wr*16..+16), wc=w>>2 (col half).
// G (banded rel GEMM, 128x64) computed by all 8 warps (16 rows each).
// Cross-warp softmax row reduce via sMax/sSum partials.
//   att[t,s] = 0.125*q[t].k[s] + rel; rel(t,t)=q[t].Er[T-1]; rel(t,t-1)=0;
//   rel(t,s)=q[s+1].Er[t-s-2] (s<=t-2):  S[r][c] += G[r-c+63][c],
//   G[a][c] = Er[d-65+a] . q[s0+1+c]   (OOB rows zero).
// ---------------------------------------------------------------------------
#define SQ_OFF    0        /* 64x68 plain fp32            */
#define SE_OFF    4352     /* 128x68 plain fp32           */
#define SK2_OFF   13056    /* float2 64x68 (split)        */
#define SQC2_OFF  21760    /* float2 64x68 (split)        */
#define SVT_OFF   30464    /* 64x68 [h][s] tf32 bits      */
#define SP_OFF    34816    /* 64x68 [r][s] tf32 bits      */
#define SG_OFF    39168    /* 128x68 fp32                 */
#define SDIAG_OFF 47872    /* 64                          */
#define SMAX_OFF  47936    /* 2x64                        */
#define SSUM_OFF  48064    /* 2x64                        */
#define SMEM_FLOATS 48192
#define SMEM_BYTES (SMEM_FLOATS*4)

__global__ __launch_bounds__(256) void attn_kernel(
    const float* __restrict__ Er,
    float* __restrict__ out)
{
    extern __shared__ float sm[];
    float*  sQ    = sm + SQ_OFF;
    float*  sE    = sm + SE_OFF;
    float2* sK2   = (float2*)(sm + SK2_OFF);
    float2* sQc2  = (float2*)(sm + SQC2_OFF);
    float*  sVt   = sm + SVT_OFF;
    float*  sP    = sm + SP_OFF;
    float*  sG    = sm + SG_OFF;
    float*  sDiag = sm + SDIAG_OFF;
    float*  sMax  = sm + SMAX_OFF;
    float*  sSum  = sm + SSUM_OFF;

    const int tid  = threadIdx.x;
    const int w    = tid >> 5;
    const int lane = tid & 31;
    const int gid  = lane >> 2;
    const int tig  = lane & 3;
    const int wr   = w & 3;
    const int wc   = w >> 2;
    const int m    = 31 - (int)blockIdx.x;     // big tiles first
    const int b    = blockIdx.y;
    const int t0   = m * 64;
    const size_t bT = (size_t)b * T_;

    {   // prologue: Q row tile (plain fp32)
        int r = tid >> 2, h0 = (tid & 3) * 16;
        const float4* qp = (const float4*)&g_q[(bT + t0 + r)*H_ + h0];
        #pragma unroll
        for (int u = 0; u < 4; ++u)
            *(float4*)&sQ[r*68 + h0 + u*4] = qp[u];
    }
    __syncthreads();

    {   // diag[r] = q[t0+r] . Er[T-1]
        int r = tid >> 2, qd = tid & 3;
        const float* er = Er + (size_t)(T_-1) * H_;
        float p = 0.f;
        #pragma unroll
        for (int hh = 0; hh < 16; ++hh) {
            int h = qd*16 + hh;
            p += sQ[r*68 + h] * er[h];
        }
        p += __shfl_xor_sync(0xffffffffu, p, 1);
        p += __shfl_xor_sync(0xffffffffu, p, 2);
        if (qd == 0) sDiag[r] = p;
    }

    float o[4][4];
    float mrow[2], lrow[2];
    #pragma unroll
    for (int n = 0; n < 4; ++n)
        #pragma unroll
        for (int j = 0; j < 4; ++j) o[n][j] = 0.f;
    mrow[0] = mrow[1] = -3.0e38f;
    lrow[0] = lrow[1] = 0.f;

    const int r0 = wr*16 + gid;

    for (int jt = 0; jt <= m; ++jt) {
        const int s0 = jt * 64;
        const int d  = t0 - s0;
        __syncthreads();   // all warps done with previous tile's smem

        {   // K (split), Qc (split), V (single tf32, transposed)
            int rr = tid >> 2, h0 = (tid & 3) * 16;
            const float4* kp = (const float4*)&g_k[(bT + s0 + rr)*H_ + h0];
            const float4* vp = (const float4*)&g_v[(bT + s0 + rr)*H_ + h0];
            int qr = s0 + 1 + rr;
            const float4* qp = (qr < T_) ? (const float4*)&g_q[(bT + qr)*H_ + h0] : 0;
            #pragma unroll
            for (int u = 0; u < 4; ++u) {
                float4 kv = kp[u];
                int h = h0 + u*4;
                sK2[rr*68 + h+0] = split_f2(kv.x);
                sK2[rr*68 + h+1] = split_f2(kv.y);
                sK2[rr*68 + h+2] = split_f2(kv.z);
                sK2[rr*68 + h+3] = split_f2(kv.w);
                float4 qv = qp ? qp[u] : make_float4(0.f,0.f,0.f,0.f);
                sQc2[rr*68 + h+0] = split_f2(qv.x);
                sQc2[rr*68 + h+1] = split_f2(qv.y);
                sQc2[rr*68 + h+2] = split_f2(qv.z);
                sQc2[rr*68 + h+3] = split_f2(qv.w);
                float4 vv = vp[u];
                sVt[(h+0)*68 + rr] = __uint_as_float(tf32_of(vv.x));
                sVt[(h+1)*68 + rr] = __uint_as_float(tf32_of(vv.y));
                sVt[(h+2)*68 + rr] = __uint_as_float(tf32_of(vv.z));
                sVt[(h+3)*68 + rr] = __uint_as_float(tf32_of(vv.w));
            }
        }
        {   // Er band (plain fp32, OOB -> 0)
            int a = tid >> 1, h0 = (tid & 1) * 32;
            int e = d - 65 + a;
            const float4* ep = (e >= 0) ? (const float4*)&Er[(size_t)e*H_ + h0] : 0;
            #pragma unroll
            for (int u = 0; u < 8; ++u) {
                float4 ev = ep ? ep[u] : make_float4(0.f,0.f,0.f,0.f);
                *(float4*)&sE[a*68 + h0 + u*4] = ev;
            }
        }
        __syncthreads();

        {   // G = ErBand(128) x Qc^T : warp w computes rows w*16..+16, all 64 cols
            float g[8][4];
            #pragma unroll
            for (int n = 0; n < 8; ++n)
                #pragma unroll
                for (int j = 0; j < 4; ++j) g[n][j] = 0.f;
            gemm_As_B2<8>(sE, w*16, sQc2, 0, lane, g);
            const int ar = w*16 + gid;
            #pragma unroll
            for (int n = 0; n < 8; ++n) {
                *(float2*)&sG[ ar   *68 + n*8 + 2*tig] = make_float2(g[n][0], g[n][1]);
                *(float2*)&sG[(ar+8)*68 + n*8 + 2*tig] = make_float2(g[n][2], g[n][3]);
            }
        }

        // S = Q x K^T : warp handles rows wr*16, col half wc
        float s[4][4];
        #pragma unroll
        for (int n = 0; n < 4; ++n)
            #pragma unroll
            for (int j = 0; j < 4; ++j) s[n][j] = 0.f;
        gemm_As_B2<4>(sQ, wr*16, sK2, wc*4, lane, s);
        __syncthreads();   // sG complete

        // gather + scale + diag/mask
        const bool dt = (jt == m);
        float mt0 = -3.0e38f, mt1 = -3.0e38f;
        #pragma unroll
        for (int n = 0; n < 4; ++n) {
            #pragma unroll
            for (int j = 0; j < 4; ++j) {
                int c = (wc*4 + n)*8 + 2*tig + (j & 1);
                int r = r0 + ((j >= 2) ? 8 : 0);
                float v = s[n][j] * 0.125f + sG[(r - c + 63)*68 + c];
                if (dt) {
                    if (c > r)       v = -3.0e38f;
                    else if (c == r) v += sDiag[r];
                }
                s[n][j] = v;
                if (j < 2) mt0 = fmaxf(mt0, v);
                else       mt1 = fmaxf(mt1, v);
            }
        }
        mt0 = fmaxf(mt0, __shfl_xor_sync(0xffffffffu, mt0, 1));
        mt0 = fmaxf(mt0, __shfl_xor_sync(0xffffffffu, mt0, 2));
        mt1 = fmaxf(mt1, __shfl_xor_sync(0xffffffffu, mt1, 1));
        mt1 = fmaxf(mt1, __shfl_xor_sync(0xffffffffu, mt1, 2));
        if (tig == 0) {
            sMax[wc*64 + r0]     = mt0;
            sMax[wc*64 + r0 + 8] = mt1;
        }
        __syncthreads();

        float mn0 = fmaxf(fmaxf(mt0, sMax[(1-wc)*64 + r0    ]), mrow[0]);
        float mn1 = fmaxf(fmaxf(mt1, sMax[(1-wc)*64 + r0 + 8]), mrow[1]);
        float cor0 = __expf(mrow[0] - mn0);
        float cor1 = __expf(mrow[1] - mn1);
        mrow[0] = mn0; mrow[1] = mn1;

        float sum0 = 0.f, sum1 = 0.f;
        #pragma unroll
        for (int n = 0; n < 4; ++n) {
            float p0 = __expf(s[n][0] - mn0);
            float p1 = __expf(s[n][1] - mn0);
            float p2 = __expf(s[n][2] - mn1);
            float p3 = __expf(s[n][3] - mn1);
            sum0 += p0 + p1; sum1 += p2 + p3;
            int c0 = (wc*4 + n)*8 + 2*tig;
            *(float2*)&sP[ r0   *68 + c0] = make_float2(
                __uint_as_float(tf32_of(p0)), __uint_as_float(tf32_of(p1)));
            *(float2*)&sP[(r0+8)*68 + c0] = make_float2(
                __uint_as_float(tf32_of(p2)), __uint_as_float(tf32_of(p3)));
            o[n][0] *= cor0; o[n][1] *= cor0;
            o[n][2] *= cor1; o[n][3] *= cor1;
        }
        sum0 += __shfl_xor_sync(0xffffffffu, sum0, 1);
        sum0 += __shfl_xor_sync(0xffffffffu, sum0, 2);
        sum1 += __shfl_xor_sync(0xffffffffu, sum1, 1);
        sum1 += __shfl_xor_sync(0xffffffffu, sum1, 2);
        if (tig == 0) {
            sSum[wc*64 + r0]     = sum0;
            sSum[wc*64 + r0 + 8] = sum1;
        }
        __syncthreads();
        lrow[0] = lrow[0]*cor0 + sum0 + sSum[(1-wc)*64 + r0];
        lrow[1] = lrow[1]*cor1 + sum1 + sSum[(1-wc)*64 + r0 + 8];

        // O += P x V (single tf32)
        gemm_pv(sP, wr*16, sVt, wc*4, lane, o);
    }

    float inv0 = 1.f / lrow[0];
    float inv1 = 1.f / lrow[1];
    #pragma unroll
    for (int n = 0; n < 4; ++n) {
        int c0 = (wc*4 + n)*8 + 2*tig;
        *(float2*)&out[(bT + t0 + r0    )*H_ + c0] =
            make_float2(o[n][0]*inv0, o[n][1]*inv0);
        *(float2*)&out[(bT + t0 + r0 + 8)*H_ + c0] =
            make_float2(o[n][2]*inv1, o[n][3]*inv1);
    }
}

// ---------------------------------------------------------------------------
extern "C" void kernel_launch(void* const* d_in, const int* in_sizes, int n_in,
                              void* d_out, int out_size)
{
    const float* x  = (const float*)d_in[0];
    const float* Wq = (const float*)d_in[1];
    const float* Wk = (const float*)d_in[2];
    const float* Wv = (const float*)d_in[3];
    const float* Er = (const float*)d_in[4];
    float* out = (float*)d_out;

    cudaFuncSetAttribute(proj_kernel,
                         cudaFuncAttributeMaxDynamicSharedMemorySize, PSMEM_BYTES);
    cudaFuncSetAttribute(attn_kernel,
                         cudaFuncAttributeMaxDynamicSharedMemorySize, SMEM_BYTES);

    proj_kernel<<<256, 256, PSMEM_BYTES>>>(x, Wq, Wk, Wv);
    attn_kernel<<<dim3(32, 16), 256, SMEM_BYTES>>>(Er, out);
}